// round 15
// baseline (speedup 1.0000x reference)
#include <cuda_runtime.h>
#include <cuda_fp16.h>
#include <cuda_fp8.h>
#include <cstdint>

#define NN 200000
#define NF 400000
#define NE (3*NF)

#define NBLK 196          // scan blocks (196*1024 >= NN)
#define KH 256            // h1 width
#define BM 64
#define NTILES (NN / BM)  // 3125
#define ASTR 264          // As/W1s row stride (halves)
#define BSTR 136          // Bs row stride (halves)

// dynamic SMEM layout (halves)
#define W1S_OFF 0
#define AS_OFF  (16 * ASTR)                 // 4224
#define BS_OFF  (AS_OFF + 64 * ASTR)        // 21120
#define SM_HALVES (BS_OFF + 256 * BSTR)     // 55936
#define SM_TOTAL (SM_HALVES * 2)            // 111872 bytes -> 2 CTAs/SM

// -------- scratch (zero-initialized at module load; every replay restores) ----
__device__ __half2 g_s1h[2 * NN];    // [2n]=(sx,sy), [2n+1]=(sz,count); reset by k_layer2
__device__ int g_flag[NBLK];         // reset inside k_scanfill (post-spin)
__device__ int g_done;               // reset by k_final
__device__ float g_gsum[128];        // reset by k_final
__device__ int g_rowptr[NN + 1];
__device__ int g_cursor[NN];
__device__ int g_aggval[NBLK];
__device__ int g_incval[NBLK];
__device__ int g_colidx[NE];
__device__ unsigned char g_t8[(size_t)NN * 128];  // 25.6 MB fp8 e4m3 (gathered 6x)
__device__ __half g_u[(size_t)NN * 128];          // 51.2 MB fp16 (streamed once)
__device__ __half g_Wc[256 * 256];                // [k][n]: fp16(W2l|W2r)

// ---- L1: face-parallel hist (half2 atomics) + fp16 weight conversion ---------
__global__ void k_hist(const int* __restrict__ face, const float* __restrict__ pos,
                       const float* __restrict__ W2l, const float* __restrict__ W2r) {
    int i = blockIdx.x * blockDim.x + threadIdx.x;
    if (i < 256 * 256) {
        int k = i >> 8, c = i & 255;
        float w = (c < 128) ? W2l[k * 128 + c] : W2r[k * 128 + (c - 128)];
        g_Wc[k * 256 + c] = __float2half_rn(w);
    }
    if (i >= NF) return;
    int v0 = face[i], v1 = face[NF + i], v2 = face[2 * NF + i];
    float p0x = pos[3 * v0 + 0], p0y = pos[3 * v0 + 1], p0z = pos[3 * v0 + 2];
    __half2 p0xy = __floats2half2_rn(p0x, p0y);
    __half2 p0zc = __floats2half2_rn(p0z, 1.0f);
    if (v0 != v1) {
        atomicAdd(&g_s1h[2 * v1 + 0], p0xy);
        atomicAdd(&g_s1h[2 * v1 + 1], p0zc);
    }
    if (v1 != v2) {
        atomicAdd(&g_s1h[2 * v2 + 0], __floats2half2_rn(pos[3 * v1 + 0], pos[3 * v1 + 1]));
        atomicAdd(&g_s1h[2 * v2 + 1], __floats2half2_rn(pos[3 * v1 + 2], 1.0f));
    }
    if (v0 != v2) {
        atomicAdd(&g_s1h[2 * v2 + 0], p0xy);
        atomicAdd(&g_s1h[2 * v2 + 1], p0zc);
    }
}

// ---- L2: fused decoupled-lookback scan + device-wide wait + CSR fill ----------
// 196 blocks x 1024 threads (co-residency 296 >= 196, same property the
// lookback already requires). After all blocks publish rowptr/cursor, a
// done-counter spin releases everyone into the fill phase.
__global__ void k_scanfill(const int* __restrict__ face) {
    __shared__ int s[1024];
    __shared__ int sprefix;
    int b = blockIdx.x;
    int tid = threadIdx.x;
    int i = b * 1024 + tid;
    int v = 0;
    if (i < NN) {
        __half2 zc = g_s1h[2 * i + 1];
        v = (int)(__half2float(__high2half(zc)) + 0.5f);
    }
    s[tid] = v;
    __syncthreads();
    #pragma unroll
    for (int off = 1; off < 1024; off <<= 1) {
        int t = (tid >= off) ? s[tid - off] : 0;
        __syncthreads();
        s[tid] += t;
        __syncthreads();
    }
    int total = s[1023];
    if (tid == 0) {
        if (b == 0) {
            g_incval[0] = total;
            __threadfence();
            atomicExch(&g_flag[0], 2);
            sprefix = 0;
        } else {
            g_aggval[b] = total;
            __threadfence();
            atomicExch(&g_flag[b], 1);
            int prefix = 0;
            int j = b - 1;
            while (j >= 0) {
                int f;
                do { f = atomicAdd(&g_flag[j], 0); } while (f == 0);
                if (f == 2) { prefix += g_incval[j]; break; }
                prefix += g_aggval[j];
                j--;
            }
            g_incval[b] = prefix + total;
            __threadfence();
            atomicExch(&g_flag[b], 2);
            sprefix = prefix;
        }
    }
    __syncthreads();
    int p = sprefix;
    if (i < NN) {
        int r = p + s[tid] - v;   // exclusive
        g_rowptr[i] = r;
        g_cursor[i] = r;
    }
    if (b == NBLK - 1 && tid == 1023) g_rowptr[NN] = p + total;
    __syncthreads();

    // device-wide completion wait
    if (tid == 0) {
        __threadfence();
        atomicAdd(&g_done, 1);
        while (atomicAdd(&g_done, 0) < NBLK) {}
    }
    __syncthreads();
    __threadfence();

    // restore scan flags (all lookback reads finished before the spin released)
    if (i < NBLK) g_flag[i] = 0;

    // fill phase: 200704 threads over 400000 faces (2 per thread)
    for (int f = i; f < NF; f += NBLK * 1024) {
        int v0 = face[f], v1 = face[NF + f], v2 = face[2 * NF + f];
        if (v0 != v1) g_colidx[atomicAdd(&g_cursor[v1], 1)] = v0;
        if (v1 != v2) g_colidx[atomicAdd(&g_cursor[v2], 1)] = v1;
        if (v0 != v2) g_colidx[atomicAdd(&g_cursor[v2], 1)] = v0;
    }
}

// ---- L3 (PROFILED): persistent N-split fused GEMM (R13 config) ---------------
// CTA owns N-half (128 of 256 outputs); Wc-half + W1 SMEM-resident; grid-strides
// over 3125 M-tiles. Phase 1: K=16 mma builds h1 (64x256) into As. Phase 2:
// K=256, zero global B traffic, zero syncs in K loop. Output: t -> fp8, u -> fp16.
__global__ void __launch_bounds__(256) k_gemm(
        const float* __restrict__ pos, const float* __restrict__ W1l,
        const float* __restrict__ W1r, const float* __restrict__ b1) {
    extern __shared__ __half sm[];
    __half* W1s = sm + W1S_OFF;   // [16][ASTR]
    __half* As  = sm + AS_OFF;    // [64][ASTR]
    __half* Bs  = sm + BS_OFF;    // [256][BSTR]  (Wc N-half, K-major)

    int tid = threadIdx.x;
    int warp = tid >> 5, lane = tid & 31;
    int wm = warp & 1;
    int wn4 = warp >> 1;          // 0..3
    int half = blockIdx.x & 1;
    int start = blockIdx.x >> 1;
    int stride = gridDim.x >> 1;

    // one-time: W1 tile (16x256; rows 0-2 W1l, 3-5 W1r, 6 b1, 7-15 = 0)
    #pragma unroll
    for (int j = 0; j < 2; j++) {
        int idx = tid + 256 * j;
        int row = idx >> 5, cq = idx & 31;
        int c = cq * 8;
        float v[8];
        #pragma unroll
        for (int q = 0; q < 8; q++) {
            float w = 0.0f;
            if (row < 3)       w = W1l[row * 256 + c + q];
            else if (row < 6)  w = W1r[(row - 3) * 256 + c + q];
            else if (row == 6) w = b1[c + q];
            v[q] = w;
        }
        __half2 h0 = __floats2half2_rn(v[0], v[1]);
        __half2 h1 = __floats2half2_rn(v[2], v[3]);
        __half2 h2 = __floats2half2_rn(v[4], v[5]);
        __half2 h3 = __floats2half2_rn(v[6], v[7]);
        *(uint4*)(W1s + row * ASTR + c) = make_uint4(*(unsigned*)&h0, *(unsigned*)&h1,
                                                     *(unsigned*)&h2, *(unsigned*)&h3);
    }
    // one-time: Wc N-half (256 x 128 fp16)
    #pragma unroll
    for (int j = 0; j < 16; j++) {
        int idx = tid + 256 * j;
        int row = idx >> 4, cq = idx & 15;
        *(uint4*)(Bs + row * BSTR + cq * 8) =
            *(const uint4*)(g_Wc + (size_t)row * 256 + half * 128 + cq * 8);
    }

    for (int mt = start; mt < NTILES; mt += stride) {
        int bm = mt * BM;
        __syncthreads();   // prior tile's phase-2 reads of As complete

        if (tid < 64) {
            int node = bm + tid;
            __half2 xy = g_s1h[2 * node + 0];
            __half2 zc = g_s1h[2 * node + 1];
            float deg = __half2float(__high2half(zc));
            float inv = 1.0f / fmaxf(deg, 1.0f);
            float ax = __half2float(__low2half(xy)) * inv;
            float ay = __half2float(__high2half(xy)) * inv;
            float az = __half2float(__low2half(zc)) * inv;
            float px = pos[3 * node + 0], py = pos[3 * node + 1], pz = pos[3 * node + 2];
            __half2 c01 = __floats2half2_rn(ax, ay);
            __half2 c23 = __floats2half2_rn(az, px);
            __half2 c45 = __floats2half2_rn(py, pz);
            __half2 c67 = __floats2half2_rn(1.0f, 0.0f);
            *(uint4*)(As + tid * ASTR + 0) = make_uint4(*(unsigned*)&c01, *(unsigned*)&c23,
                                                        *(unsigned*)&c45, *(unsigned*)&c67);
            *(uint4*)(As + tid * ASTR + 8) = make_uint4(0, 0, 0, 0);
        }
        __syncthreads();

        // phase 1: K=16 mma -> h1 fragments (full 256 cols)
        float acc[2][8][4];
        #pragma unroll
        for (int mi = 0; mi < 2; mi++)
            #pragma unroll
            for (int ni = 0; ni < 8; ni++)
                #pragma unroll
                for (int q = 0; q < 4; q++) acc[mi][ni][q] = 0.0f;
        {
            uint32_t a[2][4];
            #pragma unroll
            for (int mi = 0; mi < 2; mi++) {
                int r = wm * 32 + mi * 16 + (lane & 7) + 8 * ((lane >> 3) & 1);
                int cc = 8 * (lane >> 4);
                uint32_t addr = (uint32_t)__cvta_generic_to_shared(As + r * ASTR + cc);
                asm volatile("ldmatrix.sync.aligned.m8n8.x4.shared.b16 {%0,%1,%2,%3}, [%4];"
                             : "=r"(a[mi][0]), "=r"(a[mi][1]), "=r"(a[mi][2]), "=r"(a[mi][3])
                             : "r"(addr));
            }
            int rr = (lane & 7) + 8 * ((lane >> 3) & 1);
            #pragma unroll
            for (int np = 0; np < 4; np++) {
                int ncol = wn4 * 64 + np * 16 + 8 * (lane >> 4);
                uint32_t b[4];
                uint32_t baddr = (uint32_t)__cvta_generic_to_shared(W1s + rr * ASTR + ncol);
                asm volatile("ldmatrix.sync.aligned.m8n8.x4.trans.shared.b16 {%0,%1,%2,%3}, [%4];"
                             : "=r"(b[0]), "=r"(b[1]), "=r"(b[2]), "=r"(b[3])
                             : "r"(baddr));
                #pragma unroll
                for (int mi = 0; mi < 2; mi++) {
                    #pragma unroll
                    for (int h = 0; h < 2; h++) {
                        int ni = np * 2 + h;
                        asm volatile(
                            "mma.sync.aligned.m16n8k16.row.col.f32.f16.f16.f32 "
                            "{%0,%1,%2,%3},{%4,%5,%6,%7},{%8,%9},{%0,%1,%2,%3};"
                            : "+f"(acc[mi][ni][0]), "+f"(acc[mi][ni][1]),
                              "+f"(acc[mi][ni][2]), "+f"(acc[mi][ni][3])
                            : "r"(a[mi][0]), "r"(a[mi][1]), "r"(a[mi][2]), "r"(a[mi][3]),
                              "r"(b[2 * h]), "r"(b[2 * h + 1]));
                    }
                }
            }
        }
        __syncthreads();

        // relu + store h1 fragments into As
        {
            int gid = lane >> 2, qid = lane & 3;
            #pragma unroll
            for (int mi = 0; mi < 2; mi++) {
                int r0 = wm * 32 + mi * 16 + gid;
                int r1 = r0 + 8;
                #pragma unroll
                for (int ni = 0; ni < 8; ni++) {
                    int col = wn4 * 64 + ni * 8 + qid * 2;
                    __half2 p0 = __floats2half2_rn(fmaxf(acc[mi][ni][0], 0.0f),
                                                   fmaxf(acc[mi][ni][1], 0.0f));
                    *(unsigned*)(As + r0 * ASTR + col) = *(unsigned*)&p0;
                    __half2 p1 = __floats2half2_rn(fmaxf(acc[mi][ni][2], 0.0f),
                                                   fmaxf(acc[mi][ni][3], 0.0f));
                    *(unsigned*)(As + r1 * ASTR + col) = *(unsigned*)&p1;
                }
            }
        }
        __syncthreads();

        // phase 2: [t|u]-half = As @ Bs; K=256, all SMEM, no syncs
        #pragma unroll
        for (int mi = 0; mi < 2; mi++)
            #pragma unroll
            for (int ni = 0; ni < 4; ni++)
                #pragma unroll
                for (int q = 0; q < 4; q++) acc[mi][ni][q] = 0.0f;

        #pragma unroll 4
        for (int k0 = 0; k0 < KH; k0 += 16) {
            uint32_t a[2][4];
            #pragma unroll
            for (int mi = 0; mi < 2; mi++) {
                int r = wm * 32 + mi * 16 + (lane & 7) + 8 * ((lane >> 3) & 1);
                int cc = k0 + 8 * (lane >> 4);
                uint32_t addr = (uint32_t)__cvta_generic_to_shared(As + r * ASTR + cc);
                asm volatile("ldmatrix.sync.aligned.m8n8.x4.shared.b16 {%0,%1,%2,%3}, [%4];"
                             : "=r"(a[mi][0]), "=r"(a[mi][1]), "=r"(a[mi][2]), "=r"(a[mi][3])
                             : "r"(addr));
            }
            int rr = k0 + (lane & 7) + 8 * ((lane >> 3) & 1);
            #pragma unroll
            for (int np = 0; np < 2; np++) {
                int ncol = wn4 * 32 + np * 16 + 8 * (lane >> 4);
                uint32_t b[4];
                uint32_t baddr = (uint32_t)__cvta_generic_to_shared(Bs + rr * BSTR + ncol);
                asm volatile("ldmatrix.sync.aligned.m8n8.x4.trans.shared.b16 {%0,%1,%2,%3}, [%4];"
                             : "=r"(b[0]), "=r"(b[1]), "=r"(b[2]), "=r"(b[3])
                             : "r"(baddr));
                #pragma unroll
                for (int mi = 0; mi < 2; mi++) {
                    #pragma unroll
                    for (int h = 0; h < 2; h++) {
                        int ni = np * 2 + h;
                        asm volatile(
                            "mma.sync.aligned.m16n8k16.row.col.f32.f16.f16.f32 "
                            "{%0,%1,%2,%3},{%4,%5,%6,%7},{%8,%9},{%0,%1,%2,%3};"
                            : "+f"(acc[mi][ni][0]), "+f"(acc[mi][ni][1]),
                              "+f"(acc[mi][ni][2]), "+f"(acc[mi][ni][3])
                            : "r"(a[mi][0]), "r"(a[mi][1]), "r"(a[mi][2]), "r"(a[mi][3]),
                              "r"(b[2 * h]), "r"(b[2 * h + 1]));
                    }
                }
            }
        }

        // epilogue: half 0 -> g_t8 (fp8 e4m3), half 1 -> g_u (fp16)
        {
            int gid = lane >> 2, qid = lane & 3;
            #pragma unroll
            for (int mi = 0; mi < 2; mi++) {
                int r0 = bm + wm * 32 + mi * 16 + gid;
                int r1 = r0 + 8;
                #pragma unroll
                for (int ni = 0; ni < 4; ni++) {
                    int col = wn4 * 32 + ni * 8 + qid * 2;
                    if (half == 0) {
                        __nv_fp8x2_storage_t q0 = __nv_cvt_float2_to_fp8x2(
                            make_float2(acc[mi][ni][0], acc[mi][ni][1]),
                            __NV_SATFINITE, __NV_E4M3);
                        *(unsigned short*)(g_t8 + (size_t)r0 * 128 + col) = q0;
                        __nv_fp8x2_storage_t q1 = __nv_cvt_float2_to_fp8x2(
                            make_float2(acc[mi][ni][2], acc[mi][ni][3]),
                            __NV_SATFINITE, __NV_E4M3);
                        *(unsigned short*)(g_t8 + (size_t)r1 * 128 + col) = q1;
                    } else {
                        __half2 p0 = __floats2half2_rn(acc[mi][ni][0], acc[mi][ni][1]);
                        *(unsigned*)(g_u + (size_t)r0 * 128 + col) = *(unsigned*)&p0;
                        __half2 p1 = __floats2half2_rn(acc[mi][ni][2], acc[mi][ni][3]);
                        *(unsigned*)(g_u + (size_t)r1 * 128 + col) = *(unsigned*)&p1;
                    }
                }
            }
        }
    }
}

// ---- L4: layer-2 aggregate (fp8 gather) + relu + mean-pool (+ restore s1h) ----
__global__ void k_layer2(const float* __restrict__ b2) {
    __shared__ float gsh[128];
    if (threadIdx.x < 128) gsh[threadIdx.x] = 0.0f;
    __syncthreads();

    int wid = threadIdx.x >> 5, lane = threadIdx.x & 31;
    int gwarp = blockIdx.x * (blockDim.x >> 5) + wid;
    int nwarps = gridDim.x * (blockDim.x >> 5);
    float4 bl = ((const float4*)b2)[lane];

    float a0 = 0.f, a1 = 0.f, a2 = 0.f, a3 = 0.f;
    for (int node = gwarp; node < NN; node += nwarps) {
        int beg = g_rowptr[node], end = g_rowptr[node + 1];
        if (lane == 0) {                 // restore invariants (gemm done reading)
            g_s1h[2 * node + 0] = __floats2half2_rn(0.0f, 0.0f);
            g_s1h[2 * node + 1] = __floats2half2_rn(0.0f, 0.0f);
        }
        float s0 = 0.f, s1 = 0.f, s2 = 0.f, s3 = 0.f;
        #pragma unroll 4
        for (int j = beg; j < end; j++) {
            int src = g_colidx[j];
            unsigned tv = *(const unsigned*)(g_t8 + (size_t)src * 128 + lane * 4);
            __half2_raw r01 = __nv_cvt_fp8x2_to_halfraw2(
                (__nv_fp8x2_storage_t)(tv & 0xFFFFu), __NV_E4M3);
            __half2_raw r23 = __nv_cvt_fp8x2_to_halfraw2(
                (__nv_fp8x2_storage_t)(tv >> 16), __NV_E4M3);
            float2 t01 = __half22float2(*(__half2*)&r01);
            float2 t23 = __half22float2(*(__half2*)&r23);
            s0 += t01.x; s1 += t01.y;
            s2 += t23.x; s3 += t23.y;
        }
        float inv = 1.0f / fmaxf((float)(end - beg), 1.0f);
        uint2 uv = ((const uint2*)(g_u + (size_t)node * 128))[lane];
        float2 u01 = __half22float2(*(__half2*)&uv.x);
        float2 u23 = __half22float2(*(__half2*)&uv.y);
        a0 += fmaxf(s0 * inv + u01.x + bl.x, 0.0f);
        a1 += fmaxf(s1 * inv + u01.y + bl.y, 0.0f);
        a2 += fmaxf(s2 * inv + u23.x + bl.z, 0.0f);
        a3 += fmaxf(s3 * inv + u23.y + bl.w, 0.0f);
    }
    atomicAdd(&gsh[lane * 4 + 0], a0);
    atomicAdd(&gsh[lane * 4 + 1], a1);
    atomicAdd(&gsh[lane * 4 + 2], a2);
    atomicAdd(&gsh[lane * 4 + 3], a3);
    __syncthreads();
    if (threadIdx.x < 128) atomicAdd(&g_gsum[threadIdx.x], gsh[threadIdx.x]);
}

// ---- L5: decoder + softmax + argmax (+ restore gsum, done) --------------------
__global__ void k_final(const float* __restrict__ Wd, const float* __restrict__ bd,
                        float* __restrict__ out, int out_size) {
    if (threadIdx.x != 0 || blockIdx.x != 0) return;
    g_done = 0;   // restore invariant for scanfill spin
    float g[128];
    for (int c = 0; c < 128; c++) {
        g[c] = g_gsum[c] * (1.0f / (float)NN);
        g_gsum[c] = 0.0f;   // restore invariant
    }
    float lg[10];
    for (int j = 0; j < 10; j++) lg[j] = bd[j];
    for (int c = 0; c < 128; c++) {
        float gv = g[c];
        for (int j = 0; j < 10; j++) lg[j] += gv * Wd[c * 10 + j];
    }
    float m = lg[0];
    for (int j = 1; j < 10; j++) m = fmaxf(m, lg[j]);
    float e[10], s = 0.0f;
    for (int j = 0; j < 10; j++) { e[j] = expf(lg[j] - m); s += e[j]; }
    float invs = 1.0f / s;
    int am = 0;
    float best = -1.0f;
    for (int j = 0; j < 10; j++) {
        float p = e[j] * invs;
        if (j < out_size) out[j] = p;
        if (p > best) { best = p; am = j; }
    }
    for (int i = 10; i < out_size; i++) out[i] = (float)am;
}

// ---------------- launch --------------------------------------------------------
extern "C" void kernel_launch(void* const* d_in, const int* in_sizes, int n_in,
                              void* d_out, int out_size) {
    const float* pos = (const float*)d_in[0];
    const int*   face = (const int*)d_in[1];
    const float* W1l = (const float*)d_in[2];
    const float* W1r = (const float*)d_in[3];
    const float* b1  = (const float*)d_in[4];
    const float* W2l = (const float*)d_in[5];
    const float* W2r = (const float*)d_in[6];
    const float* b2  = (const float*)d_in[7];
    const float* Wd  = (const float*)d_in[8];
    const float* bd  = (const float*)d_in[9];
    float* out = (float*)d_out;

    int dev = 0, nsm = 148;
    cudaGetDevice(&dev);
    cudaDeviceGetAttribute(&nsm, cudaDevAttrMultiProcessorCount, dev);
    cudaFuncSetAttribute(k_gemm, cudaFuncAttributeMaxDynamicSharedMemorySize, SM_TOTAL);

    k_hist     <<<(NF + 255) / 256, 256>>>(face, pos, W2l, W2r);   // 1
    k_scanfill <<<NBLK, 1024>>>(face);                             // 2
    k_gemm     <<<2 * nsm, 256, SM_TOTAL>>>(pos, W1l, W1r, b1);    // 3
    k_layer2   <<<1184, 256>>>(b2);                                // 4  <- profiled
    k_final    <<<1, 32>>>(Wd, bd, out, out_size);                 // 5
}

// round 16
// speedup vs baseline: 1.0788x; 1.0788x over previous
#include <cuda_runtime.h>
#include <cuda_fp16.h>
#include <cuda_fp8.h>
#include <cstdint>

#define NN 200000
#define NF 400000
#define NE (3*NF)

#define NBLK 196          // scan blocks (196*1024 >= NN)
#define KH 256            // h1 width
#define BM 64
#define NTILES (NN / BM)  // 3125
#define ASTR 264          // As/W1s row stride (halves)
#define BSTR 136          // Bs row stride (halves)

// dynamic SMEM layout (halves)
#define W1S_OFF 0
#define AS_OFF  (16 * ASTR)                 // 4224
#define BS_OFF  (AS_OFF + 64 * ASTR)        // 21120
#define SM_HALVES (BS_OFF + 256 * BSTR)     // 55936
#define SM_TOTAL (SM_HALVES * 2)            // 111872 bytes -> 2 CTAs/SM

// -------- scratch (zero-initialized at module load; every replay restores) ----
__device__ __half2 g_s1h[2 * NN];    // [2n]=(sx,sy), [2n+1]=(sz,count); reset by k_layer2
__device__ int g_flag[NBLK];         // reset by k_fill
__device__ float g_gsum[128];        // reset by k_final
__device__ int g_rowptr[NN + 1];
__device__ int g_cursor[NN];
__device__ int g_aggval[NBLK];
__device__ int g_incval[NBLK];
__device__ int g_colidx[NE];
__device__ unsigned char g_t8[(size_t)NN * 128];  // 25.6 MB fp8 e4m3 (gathered 6x)
__device__ __half g_u[(size_t)NN * 128];          // 51.2 MB fp16 (streamed once)
__device__ __half g_Wc[256 * 256];                // [k][n]: fp16(W2l|W2r)

// ---- L1: face-parallel hist (half2 atomics) + fp16 weight conversion ---------
__global__ void k_hist(const int* __restrict__ face, const float* __restrict__ pos,
                       const float* __restrict__ W2l, const float* __restrict__ W2r) {
    int i = blockIdx.x * blockDim.x + threadIdx.x;
    if (i < 256 * 256) {
        int k = i >> 8, c = i & 255;
        float w = (c < 128) ? W2l[k * 128 + c] : W2r[k * 128 + (c - 128)];
        g_Wc[k * 256 + c] = __float2half_rn(w);
    }
    if (i >= NF) return;
    int v0 = face[i], v1 = face[NF + i], v2 = face[2 * NF + i];
    float p0x = pos[3 * v0 + 0], p0y = pos[3 * v0 + 1], p0z = pos[3 * v0 + 2];
    __half2 p0xy = __floats2half2_rn(p0x, p0y);
    __half2 p0zc = __floats2half2_rn(p0z, 1.0f);
    if (v0 != v1) {
        atomicAdd(&g_s1h[2 * v1 + 0], p0xy);
        atomicAdd(&g_s1h[2 * v1 + 1], p0zc);
    }
    if (v1 != v2) {
        atomicAdd(&g_s1h[2 * v2 + 0], __floats2half2_rn(pos[3 * v1 + 0], pos[3 * v1 + 1]));
        atomicAdd(&g_s1h[2 * v2 + 1], __floats2half2_rn(pos[3 * v1 + 2], 1.0f));
    }
    if (v0 != v2) {
        atomicAdd(&g_s1h[2 * v2 + 0], p0xy);
        atomicAdd(&g_s1h[2 * v2 + 1], p0zc);
    }
}

// ---- L2: single-pass decoupled-lookback scan (rowptr + cursor) ---------------
__global__ void k_scan() {
    __shared__ int s[1024];
    __shared__ int sprefix;
    int b = blockIdx.x;
    int tid = threadIdx.x;
    int i = b * 1024 + tid;
    int v = 0;
    if (i < NN) {
        __half2 zc = g_s1h[2 * i + 1];
        v = (int)(__half2float(__high2half(zc)) + 0.5f);
    }
    s[tid] = v;
    __syncthreads();
    #pragma unroll
    for (int off = 1; off < 1024; off <<= 1) {
        int t = (tid >= off) ? s[tid - off] : 0;
        __syncthreads();
        s[tid] += t;
        __syncthreads();
    }
    int total = s[1023];
    if (tid == 0) {
        if (b == 0) {
            g_incval[0] = total;
            __threadfence();
            atomicExch(&g_flag[0], 2);
            sprefix = 0;
        } else {
            g_aggval[b] = total;
            __threadfence();
            atomicExch(&g_flag[b], 1);
            int prefix = 0;
            int j = b - 1;
            while (j >= 0) {
                int f;
                do { f = atomicAdd(&g_flag[j], 0); } while (f == 0);
                if (f == 2) { prefix += g_incval[j]; break; }
                prefix += g_aggval[j];
                j--;
            }
            g_incval[b] = prefix + total;
            __threadfence();
            atomicExch(&g_flag[b], 2);
            sprefix = prefix;
        }
    }
    __syncthreads();
    int p = sprefix;
    if (i < NN) {
        int r = p + s[tid] - v;   // exclusive
        g_rowptr[i] = r;
        g_cursor[i] = r;
    }
    if (b == NBLK - 1 && tid == 1023) g_rowptr[NN] = p + total;
}

// ---- L3: fill CSR (+ restore scan flags) --------------------------------------
__global__ void k_fill(const int* __restrict__ face) {
    int i = blockIdx.x * blockDim.x + threadIdx.x;
    if (i < NBLK) g_flag[i] = 0;            // restore invariant
    if (i >= NF) return;
    int v0 = face[i], v1 = face[NF + i], v2 = face[2 * NF + i];
    if (v0 != v1) g_colidx[atomicAdd(&g_cursor[v1], 1)] = v0;
    if (v1 != v2) g_colidx[atomicAdd(&g_cursor[v2], 1)] = v1;
    if (v0 != v2) g_colidx[atomicAdd(&g_cursor[v2], 1)] = v0;
}

// ---- L4 (PROFILED): persistent N-split fused GEMM (R13 config) ---------------
__global__ void __launch_bounds__(256) k_gemm(
        const float* __restrict__ pos, const float* __restrict__ W1l,
        const float* __restrict__ W1r, const float* __restrict__ b1) {
    extern __shared__ __half sm[];
    __half* W1s = sm + W1S_OFF;   // [16][ASTR]
    __half* As  = sm + AS_OFF;    // [64][ASTR]
    __half* Bs  = sm + BS_OFF;    // [256][BSTR]  (Wc N-half, K-major)

    int tid = threadIdx.x;
    int warp = tid >> 5, lane = tid & 31;
    int wm = warp & 1;
    int wn4 = warp >> 1;          // 0..3
    int half = blockIdx.x & 1;
    int start = blockIdx.x >> 1;
    int stride = gridDim.x >> 1;

    // one-time: W1 tile (16x256; rows 0-2 W1l, 3-5 W1r, 6 b1, 7-15 = 0)
    #pragma unroll
    for (int j = 0; j < 2; j++) {
        int idx = tid + 256 * j;
        int row = idx >> 5, cq = idx & 31;
        int c = cq * 8;
        float v[8];
        #pragma unroll
        for (int q = 0; q < 8; q++) {
            float w = 0.0f;
            if (row < 3)       w = W1l[row * 256 + c + q];
            else if (row < 6)  w = W1r[(row - 3) * 256 + c + q];
            else if (row == 6) w = b1[c + q];
            v[q] = w;
        }
        __half2 h0 = __floats2half2_rn(v[0], v[1]);
        __half2 h1 = __floats2half2_rn(v[2], v[3]);
        __half2 h2 = __floats2half2_rn(v[4], v[5]);
        __half2 h3 = __floats2half2_rn(v[6], v[7]);
        *(uint4*)(W1s + row * ASTR + c) = make_uint4(*(unsigned*)&h0, *(unsigned*)&h1,
                                                     *(unsigned*)&h2, *(unsigned*)&h3);
    }
    // one-time: Wc N-half (256 x 128 fp16)
    #pragma unroll
    for (int j = 0; j < 16; j++) {
        int idx = tid + 256 * j;
        int row = idx >> 4, cq = idx & 15;
        *(uint4*)(Bs + row * BSTR + cq * 8) =
            *(const uint4*)(g_Wc + (size_t)row * 256 + half * 128 + cq * 8);
    }

    for (int mt = start; mt < NTILES; mt += stride) {
        int bm = mt * BM;
        __syncthreads();   // prior tile's phase-2 reads of As complete

        if (tid < 64) {
            int node = bm + tid;
            __half2 xy = g_s1h[2 * node + 0];
            __half2 zc = g_s1h[2 * node + 1];
            float deg = __half2float(__high2half(zc));
            float inv = 1.0f / fmaxf(deg, 1.0f);
            float ax = __half2float(__low2half(xy)) * inv;
            float ay = __half2float(__high2half(xy)) * inv;
            float az = __half2float(__low2half(zc)) * inv;
            float px = pos[3 * node + 0], py = pos[3 * node + 1], pz = pos[3 * node + 2];
            __half2 c01 = __floats2half2_rn(ax, ay);
            __half2 c23 = __floats2half2_rn(az, px);
            __half2 c45 = __floats2half2_rn(py, pz);
            __half2 c67 = __floats2half2_rn(1.0f, 0.0f);
            *(uint4*)(As + tid * ASTR + 0) = make_uint4(*(unsigned*)&c01, *(unsigned*)&c23,
                                                        *(unsigned*)&c45, *(unsigned*)&c67);
            *(uint4*)(As + tid * ASTR + 8) = make_uint4(0, 0, 0, 0);
        }
        __syncthreads();

        // phase 1: K=16 mma -> h1 fragments (full 256 cols)
        float acc[2][8][4];
        #pragma unroll
        for (int mi = 0; mi < 2; mi++)
            #pragma unroll
            for (int ni = 0; ni < 8; ni++)
                #pragma unroll
                for (int q = 0; q < 4; q++) acc[mi][ni][q] = 0.0f;
        {
            uint32_t a[2][4];
            #pragma unroll
            for (int mi = 0; mi < 2; mi++) {
                int r = wm * 32 + mi * 16 + (lane & 7) + 8 * ((lane >> 3) & 1);
                int cc = 8 * (lane >> 4);
                uint32_t addr = (uint32_t)__cvta_generic_to_shared(As + r * ASTR + cc);
                asm volatile("ldmatrix.sync.aligned.m8n8.x4.shared.b16 {%0,%1,%2,%3}, [%4];"
                             : "=r"(a[mi][0]), "=r"(a[mi][1]), "=r"(a[mi][2]), "=r"(a[mi][3])
                             : "r"(addr));
            }
            int rr = (lane & 7) + 8 * ((lane >> 3) & 1);
            #pragma unroll
            for (int np = 0; np < 4; np++) {
                int ncol = wn4 * 64 + np * 16 + 8 * (lane >> 4);
                uint32_t b[4];
                uint32_t baddr = (uint32_t)__cvta_generic_to_shared(W1s + rr * ASTR + ncol);
                asm volatile("ldmatrix.sync.aligned.m8n8.x4.trans.shared.b16 {%0,%1,%2,%3}, [%4];"
                             : "=r"(b[0]), "=r"(b[1]), "=r"(b[2]), "=r"(b[3])
                             : "r"(baddr));
                #pragma unroll
                for (int mi = 0; mi < 2; mi++) {
                    #pragma unroll
                    for (int h = 0; h < 2; h++) {
                        int ni = np * 2 + h;
                        asm volatile(
                            "mma.sync.aligned.m16n8k16.row.col.f32.f16.f16.f32 "
                            "{%0,%1,%2,%3},{%4,%5,%6,%7},{%8,%9},{%0,%1,%2,%3};"
                            : "+f"(acc[mi][ni][0]), "+f"(acc[mi][ni][1]),
                              "+f"(acc[mi][ni][2]), "+f"(acc[mi][ni][3])
                            : "r"(a[mi][0]), "r"(a[mi][1]), "r"(a[mi][2]), "r"(a[mi][3]),
                              "r"(b[2 * h]), "r"(b[2 * h + 1]));
                    }
                }
            }
        }
        __syncthreads();

        // relu + store h1 fragments into As
        {
            int gid = lane >> 2, qid = lane & 3;
            #pragma unroll
            for (int mi = 0; mi < 2; mi++) {
                int r0 = wm * 32 + mi * 16 + gid;
                int r1 = r0 + 8;
                #pragma unroll
                for (int ni = 0; ni < 8; ni++) {
                    int col = wn4 * 64 + ni * 8 + qid * 2;
                    __half2 p0 = __floats2half2_rn(fmaxf(acc[mi][ni][0], 0.0f),
                                                   fmaxf(acc[mi][ni][1], 0.0f));
                    *(unsigned*)(As + r0 * ASTR + col) = *(unsigned*)&p0;
                    __half2 p1 = __floats2half2_rn(fmaxf(acc[mi][ni][2], 0.0f),
                                                   fmaxf(acc[mi][ni][3], 0.0f));
                    *(unsigned*)(As + r1 * ASTR + col) = *(unsigned*)&p1;
                }
            }
        }
        __syncthreads();

        // phase 2: [t|u]-half = As @ Bs; K=256, all SMEM, no syncs
        #pragma unroll
        for (int mi = 0; mi < 2; mi++)
            #pragma unroll
            for (int ni = 0; ni < 4; ni++)
                #pragma unroll
                for (int q = 0; q < 4; q++) acc[mi][ni][q] = 0.0f;

        #pragma unroll 4
        for (int k0 = 0; k0 < KH; k0 += 16) {
            uint32_t a[2][4];
            #pragma unroll
            for (int mi = 0; mi < 2; mi++) {
                int r = wm * 32 + mi * 16 + (lane & 7) + 8 * ((lane >> 3) & 1);
                int cc = k0 + 8 * (lane >> 4);
                uint32_t addr = (uint32_t)__cvta_generic_to_shared(As + r * ASTR + cc);
                asm volatile("ldmatrix.sync.aligned.m8n8.x4.shared.b16 {%0,%1,%2,%3}, [%4];"
                             : "=r"(a[mi][0]), "=r"(a[mi][1]), "=r"(a[mi][2]), "=r"(a[mi][3])
                             : "r"(addr));
            }
            int rr = k0 + (lane & 7) + 8 * ((lane >> 3) & 1);
            #pragma unroll
            for (int np = 0; np < 2; np++) {
                int ncol = wn4 * 32 + np * 16 + 8 * (lane >> 4);
                uint32_t b[4];
                uint32_t baddr = (uint32_t)__cvta_generic_to_shared(Bs + rr * BSTR + ncol);
                asm volatile("ldmatrix.sync.aligned.m8n8.x4.trans.shared.b16 {%0,%1,%2,%3}, [%4];"
                             : "=r"(b[0]), "=r"(b[1]), "=r"(b[2]), "=r"(b[3])
                             : "r"(baddr));
                #pragma unroll
                for (int mi = 0; mi < 2; mi++) {
                    #pragma unroll
                    for (int h = 0; h < 2; h++) {
                        int ni = np * 2 + h;
                        asm volatile(
                            "mma.sync.aligned.m16n8k16.row.col.f32.f16.f16.f32 "
                            "{%0,%1,%2,%3},{%4,%5,%6,%7},{%8,%9},{%0,%1,%2,%3};"
                            : "+f"(acc[mi][ni][0]), "+f"(acc[mi][ni][1]),
                              "+f"(acc[mi][ni][2]), "+f"(acc[mi][ni][3])
                            : "r"(a[mi][0]), "r"(a[mi][1]), "r"(a[mi][2]), "r"(a[mi][3]),
                              "r"(b[2 * h]), "r"(b[2 * h + 1]));
                    }
                }
            }
        }

        // epilogue: half 0 -> g_t8 (fp8 e4m3), half 1 -> g_u (fp16)
        {
            int gid = lane >> 2, qid = lane & 3;
            #pragma unroll
            for (int mi = 0; mi < 2; mi++) {
                int r0 = bm + wm * 32 + mi * 16 + gid;
                int r1 = r0 + 8;
                #pragma unroll
                for (int ni = 0; ni < 4; ni++) {
                    int col = wn4 * 32 + ni * 8 + qid * 2;
                    if (half == 0) {
                        __nv_fp8x2_storage_t q0 = __nv_cvt_float2_to_fp8x2(
                            make_float2(acc[mi][ni][0], acc[mi][ni][1]),
                            __NV_SATFINITE, __NV_E4M3);
                        *(unsigned short*)(g_t8 + (size_t)r0 * 128 + col) = q0;
                        __nv_fp8x2_storage_t q1 = __nv_cvt_float2_to_fp8x2(
                            make_float2(acc[mi][ni][2], acc[mi][ni][3]),
                            __NV_SATFINITE, __NV_E4M3);
                        *(unsigned short*)(g_t8 + (size_t)r1 * 128 + col) = q1;
                    } else {
                        __half2 p0 = __floats2half2_rn(acc[mi][ni][0], acc[mi][ni][1]);
                        *(unsigned*)(g_u + (size_t)r0 * 128 + col) = *(unsigned*)&p0;
                        __half2 p1 = __floats2half2_rn(acc[mi][ni][2], acc[mi][ni][3]);
                        *(unsigned*)(g_u + (size_t)r1 * 128 + col) = *(unsigned*)&p1;
                    }
                }
            }
        }
    }
}

// ---- L5: layer-2 aggregate (fp8 gather, half2 accum) + mean-pool --------------
__global__ void k_layer2(const float* __restrict__ b2) {
    __shared__ float gsh[128];
    if (threadIdx.x < 128) gsh[threadIdx.x] = 0.0f;
    __syncthreads();

    int wid = threadIdx.x >> 5, lane = threadIdx.x & 31;
    int gwarp = blockIdx.x * (blockDim.x >> 5) + wid;
    int nwarps = gridDim.x * (blockDim.x >> 5);
    float4 bl = ((const float4*)b2)[lane];
    unsigned laneoff = lane * 4;

    float a0 = 0.f, a1 = 0.f, a2 = 0.f, a3 = 0.f;
    for (int node = gwarp; node < NN; node += nwarps) {
        int beg = g_rowptr[node], end = g_rowptr[node + 1];
        if (lane == 0) {                 // restore invariants (gemm done reading)
            g_s1h[2 * node + 0] = __floats2half2_rn(0.0f, 0.0f);
            g_s1h[2 * node + 1] = __floats2half2_rn(0.0f, 0.0f);
        }
        __half2 h01 = __floats2half2_rn(0.0f, 0.0f);
        __half2 h23 = h01;
        #pragma unroll 4
        for (int j = beg; j < end; j++) {
            unsigned off = ((unsigned)g_colidx[j] << 7) + laneoff;
            unsigned tv = *(const unsigned*)(g_t8 + off);
            __half2_raw r01 = __nv_cvt_fp8x2_to_halfraw2(
                (__nv_fp8x2_storage_t)(tv & 0xFFFFu), __NV_E4M3);
            __half2_raw r23 = __nv_cvt_fp8x2_to_halfraw2(
                (__nv_fp8x2_storage_t)(tv >> 16), __NV_E4M3);
            h01 = __hadd2(h01, *(__half2*)&r01);
            h23 = __hadd2(h23, *(__half2*)&r23);
        }
        float2 t01 = __half22float2(h01);
        float2 t23 = __half22float2(h23);
        float inv = 1.0f / fmaxf((float)(end - beg), 1.0f);
        uint2 uv = ((const uint2*)(g_u + (size_t)node * 128))[lane];
        float2 u01 = __half22float2(*(__half2*)&uv.x);
        float2 u23 = __half22float2(*(__half2*)&uv.y);
        a0 += fmaxf(t01.x * inv + u01.x + bl.x, 0.0f);
        a1 += fmaxf(t01.y * inv + u01.y + bl.y, 0.0f);
        a2 += fmaxf(t23.x * inv + u23.x + bl.z, 0.0f);
        a3 += fmaxf(t23.y * inv + u23.y + bl.w, 0.0f);
    }
    atomicAdd(&gsh[lane * 4 + 0], a0);
    atomicAdd(&gsh[lane * 4 + 1], a1);
    atomicAdd(&gsh[lane * 4 + 2], a2);
    atomicAdd(&gsh[lane * 4 + 3], a3);
    __syncthreads();
    if (threadIdx.x < 128) atomicAdd(&g_gsum[threadIdx.x], gsh[threadIdx.x]);
}

// ---- L6: decoder + softmax + argmax (+ restore gsum) ---------------------------
__global__ void k_final(const float* __restrict__ Wd, const float* __restrict__ bd,
                        float* __restrict__ out, int out_size) {
    if (threadIdx.x != 0 || blockIdx.x != 0) return;
    float g[128];
    for (int c = 0; c < 128; c++) {
        g[c] = g_gsum[c] * (1.0f / (float)NN);
        g_gsum[c] = 0.0f;   // restore invariant
    }
    float lg[10];
    for (int j = 0; j < 10; j++) lg[j] = bd[j];
    for (int c = 0; c < 128; c++) {
        float gv = g[c];
        for (int j = 0; j < 10; j++) lg[j] += gv * Wd[c * 10 + j];
    }
    float m = lg[0];
    for (int j = 1; j < 10; j++) m = fmaxf(m, lg[j]);
    float e[10], s = 0.0f;
    for (int j = 0; j < 10; j++) { e[j] = expf(lg[j] - m); s += e[j]; }
    float invs = 1.0f / s;
    int am = 0;
    float best = -1.0f;
    for (int j = 0; j < 10; j++) {
        float p = e[j] * invs;
        if (j < out_size) out[j] = p;
        if (p > best) { best = p; am = j; }
    }
    for (int i = 10; i < out_size; i++) out[i] = (float)am;
}

// ---------------- launch --------------------------------------------------------
extern "C" void kernel_launch(void* const* d_in, const int* in_sizes, int n_in,
                              void* d_out, int out_size) {
    const float* pos = (const float*)d_in[0];
    const int*   face = (const int*)d_in[1];
    const float* W1l = (const float*)d_in[2];
    const float* W1r = (const float*)d_in[3];
    const float* b1  = (const float*)d_in[4];
    const float* W2l = (const float*)d_in[5];
    const float* W2r = (const float*)d_in[6];
    const float* b2  = (const float*)d_in[7];
    const float* Wd  = (const float*)d_in[8];
    const float* bd  = (const float*)d_in[9];
    float* out = (float*)d_out;

    int dev = 0, nsm = 148;
    cudaGetDevice(&dev);
    cudaDeviceGetAttribute(&nsm, cudaDevAttrMultiProcessorCount, dev);
    cudaFuncSetAttribute(k_gemm, cudaFuncAttributeMaxDynamicSharedMemorySize, SM_TOTAL);

    k_hist   <<<(NF + 255) / 256, 256>>>(face, pos, W2l, W2r);     // 1
    k_scan   <<<NBLK, 1024>>>();                                   // 2
    k_fill   <<<(NF + 255) / 256, 256>>>(face);                    // 3
    k_gemm   <<<2 * nsm, 256, SM_TOTAL>>>(pos, W1l, W1r, b1);      // 4
    k_layer2 <<<1184, 256>>>(b2);                                  // 5
    k_final  <<<1, 32>>>(Wd, bd, out, out_size);                   // 6
}

// round 17
// speedup vs baseline: 1.1209x; 1.0391x over previous
#include <cuda_runtime.h>
#include <cuda_fp16.h>
#include <cuda_fp8.h>
#include <cstdint>

#define NN 200000
#define NF 400000
#define NE (3*NF)

#define NBLK 196          // scan blocks (196*1024 >= NN)
#define KH 256            // h1 width
#define BM 64
#define NTILES (NN / BM)  // 3125
#define ASTR 264          // As/W1s row stride (halves)
#define BSTR 136          // Bs row stride (halves)

// dynamic SMEM layout (halves)
#define W1S_OFF 0
#define AS_OFF  (16 * ASTR)                 // 4224
#define BS_OFF  (AS_OFF + 64 * ASTR)        // 21120
#define SM_HALVES (BS_OFF + 256 * BSTR)     // 55936
#define SM_TOTAL (SM_HALVES * 2)            // 111872 bytes -> 2 CTAs/SM

// -------- scratch (zero-initialized at module load; every replay restores) ----
__device__ __half2 g_s1h[2 * NN];    // [2n]=(sx,sy), [2n+1]=(sz,count); reset by k_layer2
__device__ int g_flag[NBLK];         // reset by k_fill
__device__ float g_gsum[128];        // reset by k_final
__device__ int g_rowptr[NN + 1];
__device__ int g_cursor[NN];
__device__ int g_aggval[NBLK];
__device__ int g_incval[NBLK];
__device__ int g_colidx[NE];
__device__ unsigned char g_t8[(size_t)NN * 128];  // 25.6 MB fp8 e4m3 (gathered 6x)
__device__ unsigned char g_u8[(size_t)NN * 128];  // 25.6 MB fp8 e4m3 (streamed once)

// ---- L1: face-parallel hist (half2 atomics) -----------------------------------
__global__ void k_hist(const int* __restrict__ face, const float* __restrict__ pos) {
    int i = blockIdx.x * blockDim.x + threadIdx.x;
    if (i >= NF) return;
    int v0 = face[i], v1 = face[NF + i], v2 = face[2 * NF + i];
    float p0x = pos[3 * v0 + 0], p0y = pos[3 * v0 + 1], p0z = pos[3 * v0 + 2];
    __half2 p0xy = __floats2half2_rn(p0x, p0y);
    __half2 p0zc = __floats2half2_rn(p0z, 1.0f);
    if (v0 != v1) {
        atomicAdd(&g_s1h[2 * v1 + 0], p0xy);
        atomicAdd(&g_s1h[2 * v1 + 1], p0zc);
    }
    if (v1 != v2) {
        atomicAdd(&g_s1h[2 * v2 + 0], __floats2half2_rn(pos[3 * v1 + 0], pos[3 * v1 + 1]));
        atomicAdd(&g_s1h[2 * v2 + 1], __floats2half2_rn(pos[3 * v1 + 2], 1.0f));
    }
    if (v0 != v2) {
        atomicAdd(&g_s1h[2 * v2 + 0], p0xy);
        atomicAdd(&g_s1h[2 * v2 + 1], p0zc);
    }
}

// ---- L2: single-pass decoupled-lookback scan (rowptr + cursor) ---------------
__global__ void k_scan() {
    __shared__ int s[1024];
    __shared__ int sprefix;
    int b = blockIdx.x;
    int tid = threadIdx.x;
    int i = b * 1024 + tid;
    int v = 0;
    if (i < NN) {
        __half2 zc = g_s1h[2 * i + 1];
        v = (int)(__half2float(__high2half(zc)) + 0.5f);
    }
    s[tid] = v;
    __syncthreads();
    #pragma unroll
    for (int off = 1; off < 1024; off <<= 1) {
        int t = (tid >= off) ? s[tid - off] : 0;
        __syncthreads();
        s[tid] += t;
        __syncthreads();
    }
    int total = s[1023];
    if (tid == 0) {
        if (b == 0) {
            g_incval[0] = total;
            __threadfence();
            atomicExch(&g_flag[0], 2);
            sprefix = 0;
        } else {
            g_aggval[b] = total;
            __threadfence();
            atomicExch(&g_flag[b], 1);
            int prefix = 0;
            int j = b - 1;
            while (j >= 0) {
                int f;
                do { f = atomicAdd(&g_flag[j], 0); } while (f == 0);
                if (f == 2) { prefix += g_incval[j]; break; }
                prefix += g_aggval[j];
                j--;
            }
            g_incval[b] = prefix + total;
            __threadfence();
            atomicExch(&g_flag[b], 2);
            sprefix = prefix;
        }
    }
    __syncthreads();
    int p = sprefix;
    if (i < NN) {
        int r = p + s[tid] - v;   // exclusive
        g_rowptr[i] = r;
        g_cursor[i] = r;
    }
    if (b == NBLK - 1 && tid == 1023) g_rowptr[NN] = p + total;
}

// ---- L3: fill CSR (+ restore scan flags) --------------------------------------
__global__ void k_fill(const int* __restrict__ face) {
    int i = blockIdx.x * blockDim.x + threadIdx.x;
    if (i < NBLK) g_flag[i] = 0;            // restore invariant
    if (i >= NF) return;
    int v0 = face[i], v1 = face[NF + i], v2 = face[2 * NF + i];
    if (v0 != v1) g_colidx[atomicAdd(&g_cursor[v1], 1)] = v0;
    if (v1 != v2) g_colidx[atomicAdd(&g_cursor[v2], 1)] = v1;
    if (v0 != v2) g_colidx[atomicAdd(&g_cursor[v2], 1)] = v0;
}

// ---- L4 (PROFILED): persistent N-split fused GEMM -----------------------------
// CTA owns N-half (128 of 256 outputs); W2-half (converted fp32->fp16 in-regs)
// + W1 SMEM-resident; grid-strides over 3125 M-tiles. Phase 1: K=16 mma builds
// h1 (64x256) into As. Phase 2: K=256, zero global B traffic, zero syncs in the
// K loop. Output: both halves fp8 e4m3 (t -> g_t8, u -> g_u8).
__global__ void __launch_bounds__(256) k_gemm(
        const float* __restrict__ pos, const float* __restrict__ W1l,
        const float* __restrict__ W1r, const float* __restrict__ b1,
        const float* __restrict__ W2l, const float* __restrict__ W2r) {
    extern __shared__ __half sm[];
    __half* W1s = sm + W1S_OFF;   // [16][ASTR]
    __half* As  = sm + AS_OFF;    // [64][ASTR]
    __half* Bs  = sm + BS_OFF;    // [256][BSTR]  (W2 N-half, K-major)

    int tid = threadIdx.x;
    int warp = tid >> 5, lane = tid & 31;
    int wm = warp & 1;
    int wn4 = warp >> 1;          // 0..3
    int half = blockIdx.x & 1;
    int start = blockIdx.x >> 1;
    int stride = gridDim.x >> 1;

    // one-time: W1 tile (16x256; rows 0-2 W1l, 3-5 W1r, 6 b1, 7-15 = 0)
    #pragma unroll
    for (int j = 0; j < 2; j++) {
        int idx = tid + 256 * j;
        int row = idx >> 5, cq = idx & 31;
        int c = cq * 8;
        float v[8];
        #pragma unroll
        for (int q = 0; q < 8; q++) {
            float w = 0.0f;
            if (row < 3)       w = W1l[row * 256 + c + q];
            else if (row < 6)  w = W1r[(row - 3) * 256 + c + q];
            else if (row == 6) w = b1[c + q];
            v[q] = w;
        }
        __half2 h0 = __floats2half2_rn(v[0], v[1]);
        __half2 h1 = __floats2half2_rn(v[2], v[3]);
        __half2 h2 = __floats2half2_rn(v[4], v[5]);
        __half2 h3 = __floats2half2_rn(v[6], v[7]);
        *(uint4*)(W1s + row * ASTR + c) = make_uint4(*(unsigned*)&h0, *(unsigned*)&h1,
                                                     *(unsigned*)&h2, *(unsigned*)&h3);
    }
    // one-time: W2 N-half (256 x 128), fp32 -> fp16 in registers
    {
        const float* Wsrc = half ? W2r : W2l;
        #pragma unroll
        for (int j = 0; j < 32; j++) {
            int idx = tid + 256 * j;        // 8192 float4
            int row = idx >> 5, cq = idx & 31;
            float4 v = *(const float4*)(Wsrc + (size_t)row * 128 + cq * 4);
            __half2 a = __floats2half2_rn(v.x, v.y);
            __half2 b = __floats2half2_rn(v.z, v.w);
            *(uint2*)(Bs + row * BSTR + cq * 4) = make_uint2(*(unsigned*)&a, *(unsigned*)&b);
        }
    }

    for (int mt = start; mt < NTILES; mt += stride) {
        int bm = mt * BM;
        __syncthreads();   // prior tile's phase-2 reads of As complete

        if (tid < 64) {
            int node = bm + tid;
            __half2 xy = g_s1h[2 * node + 0];
            __half2 zc = g_s1h[2 * node + 1];
            float deg = __half2float(__high2half(zc));
            float inv = 1.0f / fmaxf(deg, 1.0f);
            float ax = __half2float(__low2half(xy)) * inv;
            float ay = __half2float(__high2half(xy)) * inv;
            float az = __half2float(__low2half(zc)) * inv;
            float px = pos[3 * node + 0], py = pos[3 * node + 1], pz = pos[3 * node + 2];
            __half2 c01 = __floats2half2_rn(ax, ay);
            __half2 c23 = __floats2half2_rn(az, px);
            __half2 c45 = __floats2half2_rn(py, pz);
            __half2 c67 = __floats2half2_rn(1.0f, 0.0f);
            *(uint4*)(As + tid * ASTR + 0) = make_uint4(*(unsigned*)&c01, *(unsigned*)&c23,
                                                        *(unsigned*)&c45, *(unsigned*)&c67);
            *(uint4*)(As + tid * ASTR + 8) = make_uint4(0, 0, 0, 0);
        }
        __syncthreads();

        // phase 1: K=16 mma -> h1 fragments (full 256 cols)
        float acc[2][8][4];
        #pragma unroll
        for (int mi = 0; mi < 2; mi++)
            #pragma unroll
            for (int ni = 0; ni < 8; ni++)
                #pragma unroll
                for (int q = 0; q < 4; q++) acc[mi][ni][q] = 0.0f;
        {
            uint32_t a[2][4];
            #pragma unroll
            for (int mi = 0; mi < 2; mi++) {
                int r = wm * 32 + mi * 16 + (lane & 7) + 8 * ((lane >> 3) & 1);
                int cc = 8 * (lane >> 4);
                uint32_t addr = (uint32_t)__cvta_generic_to_shared(As + r * ASTR + cc);
                asm volatile("ldmatrix.sync.aligned.m8n8.x4.shared.b16 {%0,%1,%2,%3}, [%4];"
                             : "=r"(a[mi][0]), "=r"(a[mi][1]), "=r"(a[mi][2]), "=r"(a[mi][3])
                             : "r"(addr));
            }
            int rr = (lane & 7) + 8 * ((lane >> 3) & 1);
            #pragma unroll
            for (int np = 0; np < 4; np++) {
                int ncol = wn4 * 64 + np * 16 + 8 * (lane >> 4);
                uint32_t b[4];
                uint32_t baddr = (uint32_t)__cvta_generic_to_shared(W1s + rr * ASTR + ncol);
                asm volatile("ldmatrix.sync.aligned.m8n8.x4.trans.shared.b16 {%0,%1,%2,%3}, [%4];"
                             : "=r"(b[0]), "=r"(b[1]), "=r"(b[2]), "=r"(b[3])
                             : "r"(baddr));
                #pragma unroll
                for (int mi = 0; mi < 2; mi++) {
                    #pragma unroll
                    for (int h = 0; h < 2; h++) {
                        int ni = np * 2 + h;
                        asm volatile(
                            "mma.sync.aligned.m16n8k16.row.col.f32.f16.f16.f32 "
                            "{%0,%1,%2,%3},{%4,%5,%6,%7},{%8,%9},{%0,%1,%2,%3};"
                            : "+f"(acc[mi][ni][0]), "+f"(acc[mi][ni][1]),
                              "+f"(acc[mi][ni][2]), "+f"(acc[mi][ni][3])
                            : "r"(a[mi][0]), "r"(a[mi][1]), "r"(a[mi][2]), "r"(a[mi][3]),
                              "r"(b[2 * h]), "r"(b[2 * h + 1]));
                    }
                }
            }
        }
        __syncthreads();

        // relu + store h1 fragments into As
        {
            int gid = lane >> 2, qid = lane & 3;
            #pragma unroll
            for (int mi = 0; mi < 2; mi++) {
                int r0 = wm * 32 + mi * 16 + gid;
                int r1 = r0 + 8;
                #pragma unroll
                for (int ni = 0; ni < 8; ni++) {
                    int col = wn4 * 64 + ni * 8 + qid * 2;
                    __half2 p0 = __floats2half2_rn(fmaxf(acc[mi][ni][0], 0.0f),
                                                   fmaxf(acc[mi][ni][1], 0.0f));
                    *(unsigned*)(As + r0 * ASTR + col) = *(unsigned*)&p0;
                    __half2 p1 = __floats2half2_rn(fmaxf(acc[mi][ni][2], 0.0f),
                                                   fmaxf(acc[mi][ni][3], 0.0f));
                    *(unsigned*)(As + r1 * ASTR + col) = *(unsigned*)&p1;
                }
            }
        }
        __syncthreads();

        // phase 2: [t|u]-half = As @ Bs; K=256, all SMEM, no syncs
        #pragma unroll
        for (int mi = 0; mi < 2; mi++)
            #pragma unroll
            for (int ni = 0; ni < 4; ni++)
                #pragma unroll
                for (int q = 0; q < 4; q++) acc[mi][ni][q] = 0.0f;

        #pragma unroll 4
        for (int k0 = 0; k0 < KH; k0 += 16) {
            uint32_t a[2][4];
            #pragma unroll
            for (int mi = 0; mi < 2; mi++) {
                int r = wm * 32 + mi * 16 + (lane & 7) + 8 * ((lane >> 3) & 1);
                int cc = k0 + 8 * (lane >> 4);
                uint32_t addr = (uint32_t)__cvta_generic_to_shared(As + r * ASTR + cc);
                asm volatile("ldmatrix.sync.aligned.m8n8.x4.shared.b16 {%0,%1,%2,%3}, [%4];"
                             : "=r"(a[mi][0]), "=r"(a[mi][1]), "=r"(a[mi][2]), "=r"(a[mi][3])
                             : "r"(addr));
            }
            int rr = k0 + (lane & 7) + 8 * ((lane >> 3) & 1);
            #pragma unroll
            for (int np = 0; np < 2; np++) {
                int ncol = wn4 * 32 + np * 16 + 8 * (lane >> 4);
                uint32_t b[4];
                uint32_t baddr = (uint32_t)__cvta_generic_to_shared(Bs + rr * BSTR + ncol);
                asm volatile("ldmatrix.sync.aligned.m8n8.x4.trans.shared.b16 {%0,%1,%2,%3}, [%4];"
                             : "=r"(b[0]), "=r"(b[1]), "=r"(b[2]), "=r"(b[3])
                             : "r"(baddr));
                #pragma unroll
                for (int mi = 0; mi < 2; mi++) {
                    #pragma unroll
                    for (int h = 0; h < 2; h++) {
                        int ni = np * 2 + h;
                        asm volatile(
                            "mma.sync.aligned.m16n8k16.row.col.f32.f16.f16.f32 "
                            "{%0,%1,%2,%3},{%4,%5,%6,%7},{%8,%9},{%0,%1,%2,%3};"
                            : "+f"(acc[mi][ni][0]), "+f"(acc[mi][ni][1]),
                              "+f"(acc[mi][ni][2]), "+f"(acc[mi][ni][3])
                            : "r"(a[mi][0]), "r"(a[mi][1]), "r"(a[mi][2]), "r"(a[mi][3]),
                              "r"(b[2 * h]), "r"(b[2 * h + 1]));
                    }
                }
            }
        }

        // epilogue: fp8 e4m3 store; half 0 -> g_t8, half 1 -> g_u8
        {
            unsigned char* dst = half ? g_u8 : g_t8;
            int gid = lane >> 2, qid = lane & 3;
            #pragma unroll
            for (int mi = 0; mi < 2; mi++) {
                int r0 = bm + wm * 32 + mi * 16 + gid;
                int r1 = r0 + 8;
                #pragma unroll
                for (int ni = 0; ni < 4; ni++) {
                    int col = wn4 * 32 + ni * 8 + qid * 2;
                    __nv_fp8x2_storage_t q0 = __nv_cvt_float2_to_fp8x2(
                        make_float2(acc[mi][ni][0], acc[mi][ni][1]),
                        __NV_SATFINITE, __NV_E4M3);
                    *(unsigned short*)(dst + (size_t)r0 * 128 + col) = q0;
                    __nv_fp8x2_storage_t q1 = __nv_cvt_float2_to_fp8x2(
                        make_float2(acc[mi][ni][2], acc[mi][ni][3]),
                        __NV_SATFINITE, __NV_E4M3);
                    *(unsigned short*)(dst + (size_t)r1 * 128 + col) = q1;
                }
            }
        }
    }
}

// ---- L5: layer-2 aggregate (fp8 gather, half2 accum) + mean-pool --------------
__global__ void k_layer2(const float* __restrict__ b2) {
    __shared__ float gsh[128];
    if (threadIdx.x < 128) gsh[threadIdx.x] = 0.0f;
    __syncthreads();

    int wid = threadIdx.x >> 5, lane = threadIdx.x & 31;
    int gwarp = blockIdx.x * (blockDim.x >> 5) + wid;
    int nwarps = gridDim.x * (blockDim.x >> 5);
    float4 bl = ((const float4*)b2)[lane];
    unsigned laneoff = lane * 4;

    float a0 = 0.f, a1 = 0.f, a2 = 0.f, a3 = 0.f;
    for (int node = gwarp; node < NN; node += nwarps) {
        int beg = g_rowptr[node], end = g_rowptr[node + 1];
        if (lane == 0) {                 // restore invariants (gemm done reading)
            g_s1h[2 * node + 0] = __floats2half2_rn(0.0f, 0.0f);
            g_s1h[2 * node + 1] = __floats2half2_rn(0.0f, 0.0f);
        }
        __half2 h01 = __floats2half2_rn(0.0f, 0.0f);
        __half2 h23 = h01;
        #pragma unroll 4
        for (int j = beg; j < end; j++) {
            unsigned off = ((unsigned)g_colidx[j] << 7) + laneoff;
            unsigned tv = *(const unsigned*)(g_t8 + off);
            __half2_raw r01 = __nv_cvt_fp8x2_to_halfraw2(
                (__nv_fp8x2_storage_t)(tv & 0xFFFFu), __NV_E4M3);
            __half2_raw r23 = __nv_cvt_fp8x2_to_halfraw2(
                (__nv_fp8x2_storage_t)(tv >> 16), __NV_E4M3);
            h01 = __hadd2(h01, *(__half2*)&r01);
            h23 = __hadd2(h23, *(__half2*)&r23);
        }
        float2 t01 = __half22float2(h01);
        float2 t23 = __half22float2(h23);
        float inv = 1.0f / fmaxf((float)(end - beg), 1.0f);
        unsigned uu = *(const unsigned*)(g_u8 + ((unsigned)node << 7) + laneoff);
        __half2_raw s01 = __nv_cvt_fp8x2_to_halfraw2(
            (__nv_fp8x2_storage_t)(uu & 0xFFFFu), __NV_E4M3);
        __half2_raw s23 = __nv_cvt_fp8x2_to_halfraw2(
            (__nv_fp8x2_storage_t)(uu >> 16), __NV_E4M3);
        float2 u01 = __half22float2(*(__half2*)&s01);
        float2 u23 = __half22float2(*(__half2*)&s23);
        a0 += fmaxf(t01.x * inv + u01.x + bl.x, 0.0f);
        a1 += fmaxf(t01.y * inv + u01.y + bl.y, 0.0f);
        a2 += fmaxf(t23.x * inv + u23.x + bl.z, 0.0f);
        a3 += fmaxf(t23.y * inv + u23.y + bl.w, 0.0f);
    }
    atomicAdd(&gsh[lane * 4 + 0], a0);
    atomicAdd(&gsh[lane * 4 + 1], a1);
    atomicAdd(&gsh[lane * 4 + 2], a2);
    atomicAdd(&gsh[lane * 4 + 3], a3);
    __syncthreads();
    if (threadIdx.x < 128) atomicAdd(&g_gsum[threadIdx.x], gsh[threadIdx.x]);
}

// ---- L6: decoder + softmax + argmax (+ restore gsum) ---------------------------
__global__ void k_final(const float* __restrict__ Wd, const float* __restrict__ bd,
                        float* __restrict__ out, int out_size) {
    if (threadIdx.x != 0 || blockIdx.x != 0) return;
    float g[128];
    for (int c = 0; c < 128; c++) {
        g[c] = g_gsum[c] * (1.0f / (float)NN);
        g_gsum[c] = 0.0f;   // restore invariant
    }
    float lg[10];
    for (int j = 0; j < 10; j++) lg[j] = bd[j];
    for (int c = 0; c < 128; c++) {
        float gv = g[c];
        for (int j = 0; j < 10; j++) lg[j] += gv * Wd[c * 10 + j];
    }
    float m = lg[0];
    for (int j = 1; j < 10; j++) m = fmaxf(m, lg[j]);
    float e[10], s = 0.0f;
    for (int j = 0; j < 10; j++) { e[j] = expf(lg[j] - m); s += e[j]; }
    float invs = 1.0f / s;
    int am = 0;
    float best = -1.0f;
    for (int j = 0; j < 10; j++) {
        float p = e[j] * invs;
        if (j < out_size) out[j] = p;
        if (p > best) { best = p; am = j; }
    }
    for (int i = 10; i < out_size; i++) out[i] = (float)am;
}

// ---------------- launch --------------------------------------------------------
extern "C" void kernel_launch(void* const* d_in, const int* in_sizes, int n_in,
                              void* d_out, int out_size) {
    const float* pos = (const float*)d_in[0];
    const int*   face = (const int*)d_in[1];
    const float* W1l = (const float*)d_in[2];
    const float* W1r = (const float*)d_in[3];
    const float* b1  = (const float*)d_in[4];
    const float* W2l = (const float*)d_in[5];
    const float* W2r = (const float*)d_in[6];
    const float* b2  = (const float*)d_in[7];
    const float* Wd  = (const float*)d_in[8];
    const float* bd  = (const float*)d_in[9];
    float* out = (float*)d_out;

    int dev = 0, nsm = 148;
    cudaGetDevice(&dev);
    cudaDeviceGetAttribute(&nsm, cudaDevAttrMultiProcessorCount, dev);
    cudaFuncSetAttribute(k_gemm, cudaFuncAttributeMaxDynamicSharedMemorySize, SM_TOTAL);

    k_hist   <<<(NF + 255) / 256, 256>>>(face, pos);                    // 1
    k_scan   <<<NBLK, 1024>>>();                                        // 2
    k_fill   <<<(NF + 255) / 256, 256>>>(face);                         // 3
    k_gemm   <<<2 * nsm, 256, SM_TOTAL>>>(pos, W1l, W1r, b1, W2l, W2r); // 4
    k_layer2 <<<1184, 256>>>(b2);                                       // 5
    k_final  <<<1, 32>>>(Wd, bd, out, out_size);                        // 6
}